// round 13
// baseline (speedup 1.0000x reference)
#include <cuda_runtime.h>
#include <math.h>

#define NPROB  64
#define NRR    8
#define NK     500
#define HDIM   256
#define NHEADS 8
#define HD     32
#define BATCH  512   // NPROB*NRR
#define KQ     125   // NK / 4 k-split for glimpse
#define NSPLIT 4
#define QKS    4     // qproj K-split

// ---------------- scratch (no allocations allowed) ----------------
__device__ float g_WT[512 * 1024];                     // [k][j] transposed LSTM weights
__device__ float g_qm_part[4 * BATCH * HDIM];          // [kq][b][j]
__device__ float g_lstm_part[4 * BATCH * 4 * HDIM];    // [kq][b][1024]
__device__ float g_Qpart[QKS * NHEADS * BATCH * HD];   // [kq][a][pq][d]
__device__ float g_logit[BATCH * NK];
__device__ unsigned char g_mask[BATCH * NK];
__device__ float g_att_part[NSPLIT * NHEADS * NPROB * NRR * HD];
__device__ float2 g_att_ms[NSPLIT * NHEADS * NPROB * NRR];

__device__ __forceinline__ float fast_tanh(float x) {
    float y;
    asm("tanh.approx.f32 %0, %1;" : "=f"(y) : "f"(x));
    return y;
}
__device__ __forceinline__ float tanh_acc(float x) {
    float e = __expf(2.0f * x);
    return 1.0f - __fdividef(2.0f, e + 1.0f);
}
__device__ __forceinline__ float sigmoidf_(float x) {
    return 1.0f / (1.0f + __expf(-x));
}

// =================================================================
// Kernel 0: transpose LSTM weights into g_WT[k][j].
// =================================================================
__global__ __launch_bounds__(256)
void wt_kernel(const float* __restrict__ W_ih, const float* __restrict__ W_hh)
{
    __shared__ float tile[32][33];
    const int t = threadIdx.x, tx = t & 31, ty = t >> 5;
    const int j0 = blockIdx.x * 32, k0 = blockIdx.y * 32;
    const float* W = (k0 < 256) ? W_ih : W_hh;
    const int kk0 = k0 & 255;
#pragma unroll
    for (int r = ty; r < 32; r += 8)
        tile[r][tx] = W[(j0 + r) * 256 + kk0 + tx];
    __syncthreads();
#pragma unroll
    for (int r = ty; r < 32; r += 8)
        g_WT[(k0 + r) * 1024 + j0 + tx] = tile[tx][r];
}

// =================================================================
// Kernel 1a: LSTM partial GEMM, k-split 4, register-tiled.
// Thread = 4 rows x 4 contiguous j -> 16 FMA per LDG.128.
// Also: distributed mask detect+normalize preamble (500/block).
// =================================================================
__global__ __launch_bounds__(256)
void lstm_part_kernel(const float* __restrict__ query, const float* __restrict__ state1,
                      const void* __restrict__ mraw)
{
    __shared__ float A_s[32 * 132];
    __shared__ int s_i32, s_f32, s_bf16;
    const int t  = threadIdx.x;
    const int b0 = blockIdx.x * 32;
    const int j0 = blockIdx.y * 128;
    const int kq = blockIdx.z;

    if (t == 0) { s_i32 = 1; s_f32 = 1; s_bf16 = 1; }
    __syncthreads();
    {
        const unsigned int* mw = (const unsigned int*)mraw;
        int ok_i32 = 1, ok_f32 = 1, ok_bf16 = 1;
        for (int i = t; i < 2000; i += 256) {
            unsigned int w = mw[i];
            ok_i32  &= (w <= 1u);
            ok_f32  &= (w == 0u || w == 0x3F800000u);
            unsigned int lo = w & 0xFFFFu, hi = w >> 16;
            ok_bf16 &= (lo == 0u || lo == 0x3F80u) && (hi == 0u || hi == 0x3F80u);
        }
        if (!ok_i32)  atomicAnd(&s_i32, 0);
        if (!ok_f32)  atomicAnd(&s_f32, 0);
        if (!ok_bf16) atomicAnd(&s_bf16, 0);
    }

    const float* Asrc = ((kq < 2) ? query : state1) + (kq & 1) * 128;
    for (int i = t; i < 1024; i += 256) {
        int r = i >> 5, c4 = (i & 31) * 4;
        *(float4*)&A_s[r * 132 + c4] = *(const float4*)&Asrc[(b0 + r) * 256 + c4];
    }
    __syncthreads();

    {
        int mode = 0;
        if (s_i32) mode = 1;
        else if (s_f32) mode = 2;
        else if (s_bf16) mode = 3;
        const int bid = (blockIdx.z * 8 + blockIdx.y) * 16 + blockIdx.x;
        const int base = bid * 500;
        for (int i = t; i < 500; i += 256) {
            int idx = base + i;
            unsigned char v;
            if (mode == 1)      v = (((const int*)mraw)[idx] != 0);
            else if (mode == 2) v = (((const unsigned int*)mraw)[idx] != 0u);
            else if (mode == 3) v = (((const unsigned short*)mraw)[idx] != 0u);
            else                v = (((const unsigned char*)mraw)[idx] != 0u);
            g_mask[idx] = v;
        }
    }

    const int w = t >> 5, l = t & 31;
    const int r0 = w * 4;
    const float* Wp = g_WT + (kq * 128) * 1024 + j0 + l * 4;
    float4 acc0 = make_float4(0, 0, 0, 0);
    float4 acc1 = make_float4(0, 0, 0, 0);
    float4 acc2 = make_float4(0, 0, 0, 0);
    float4 acc3 = make_float4(0, 0, 0, 0);
#pragma unroll 4
    for (int k = 0; k < 128; k++) {
        float4 wv = *(const float4*)&Wp[k * 1024];
        float a0 = A_s[(r0 + 0) * 132 + k];
        float a1 = A_s[(r0 + 1) * 132 + k];
        float a2 = A_s[(r0 + 2) * 132 + k];
        float a3 = A_s[(r0 + 3) * 132 + k];
        acc0.x += a0 * wv.x; acc0.y += a0 * wv.y; acc0.z += a0 * wv.z; acc0.w += a0 * wv.w;
        acc1.x += a1 * wv.x; acc1.y += a1 * wv.y; acc1.z += a1 * wv.z; acc1.w += a1 * wv.w;
        acc2.x += a2 * wv.x; acc2.y += a2 * wv.y; acc2.z += a2 * wv.z; acc2.w += a2 * wv.w;
        acc3.x += a3 * wv.x; acc3.y += a3 * wv.y; acc3.z += a3 * wv.z; acc3.w += a3 * wv.w;
    }
    float* outp = g_lstm_part + kq * (BATCH * 1024) + (b0 + r0) * 1024 + j0 + l * 4;
    *(float4*)&outp[0]    = acc0;
    *(float4*)&outp[1024] = acc1;
    *(float4*)&outp[2048] = acc2;
    *(float4*)&outp[3072] = acc3;
}

// =================================================================
// Kernel 1b: LSTM pointwise: combine 4 k-partials + biases, gates.
// =================================================================
__global__ __launch_bounds__(256)
void lstm_point_kernel(const float* __restrict__ state2,
                       const float* __restrict__ b_ih, const float* __restrict__ b_hh,
                       float* __restrict__ out_h, float* __restrict__ out_c)
{
    const int v = blockIdx.x * 256 + threadIdx.x;
    const int b = v >> 6, jv = v & 63;
    const float4* bi = (const float4*)b_ih;
    const float4* bh = (const float4*)b_hh;
    float4 g[4];
#pragma unroll
    for (int gg = 0; gg < 4; gg++) {
        float4 s = bi[gg * 64 + jv], s2 = bh[gg * 64 + jv];
        g[gg] = make_float4(s.x + s2.x, s.y + s2.y, s.z + s2.z, s.w + s2.w);
    }
#pragma unroll
    for (int s = 0; s < 4; s++) {
        const float4* P = (const float4*)(g_lstm_part + s * (BATCH * 1024) + b * 1024);
#pragma unroll
        for (int gg = 0; gg < 4; gg++) {
            float4 pv = P[gg * 64 + jv];
            g[gg].x += pv.x; g[gg].y += pv.y; g[gg].z += pv.z; g[gg].w += pv.w;
        }
    }
    float4 s2 = ((const float4*)state2)[b * 64 + jv];
    float4 c4, h4;
    c4.x = sigmoidf_(g[1].x) * s2.x + sigmoidf_(g[0].x) * tanh_acc(g[2].x);
    c4.y = sigmoidf_(g[1].y) * s2.y + sigmoidf_(g[0].y) * tanh_acc(g[2].y);
    c4.z = sigmoidf_(g[1].z) * s2.z + sigmoidf_(g[0].z) * tanh_acc(g[2].z);
    c4.w = sigmoidf_(g[1].w) * s2.w + sigmoidf_(g[0].w) * tanh_acc(g[2].w);
    h4.x = sigmoidf_(g[3].x) * tanh_acc(c4.x);
    h4.y = sigmoidf_(g[3].y) * tanh_acc(c4.y);
    h4.z = sigmoidf_(g[3].z) * tanh_acc(c4.z);
    h4.w = sigmoidf_(g[3].w) * tanh_acc(c4.w);
    ((float4*)out_h)[b * 64 + jv] = h4;
    ((float4*)out_c)[b * 64 + jv] = c4;
}

// =================================================================
// Kernel 1.5: qproj, register-tiled lanes.  grid 512 x 256 thr.
// warp = 4 rows x 8 d4-groups; per h: 1 h-LDG (4 sectors) +
// 1 Q-LDG.128 (128B) + 4 FMA/lane.  Total warp-LDG / 4 vs R12.
// =================================================================
__global__ __launch_bounds__(256)
void qproj_kernel(const float* __restrict__ h_in, const float* __restrict__ nn_Q)
{
    const int blk = blockIdx.x;
    const int rt = blk & 15;
    const int a  = (blk >> 4) & 7;
    const int kq = blk >> 7;
    const int t = threadIdx.x;
    const int w = t >> 5, l = t & 31;
    const int rloc = l >> 3, d4 = (l & 7) * 4;
    const int r = rt * 32 + w * 4 + rloc;

    const float* hp = h_in + r * 256 + kq * 64;
    const float* Qp = nn_Q + a * 8192 + (kq * 64) * 32 + d4;
    float4 acc = make_float4(0, 0, 0, 0);
#pragma unroll 8
    for (int h = 0; h < 64; h++) {
        float hv = hp[h];
        float4 qv = *(const float4*)&Qp[h * 32];
        acc.x += hv * qv.x; acc.y += hv * qv.y;
        acc.z += hv * qv.z; acc.w += hv * qv.w;
    }
    *(float4*)&g_Qpart[((kq * 8 + a) * 512 + r) * 32 + d4] = acc;
}

// =================================================================
// Kernel 2: glimpse partials, software-pipelined (double-buffered
// K_s, register prefetch of next chunk before computing current).
// block = (quarter, head a, problem p), grid 2048.
// =================================================================
__global__ __launch_bounds__(256)
void glimpse_part_kernel(const float* __restrict__ Kt, const float* __restrict__ Vt)
{
    __shared__ __align__(16) float Q_s[8 * 32];
    __shared__ float S_s[8 * 128];
    __shared__ __align__(16) float K_s[2][64 * 36];

    const int t = threadIdx.x;
    const int quarter = blockIdx.x >> 9;
    const int a = (blockIdx.x >> 6) & 7;
    const int p = blockIdx.x & 63;
    const int kb = (a * 64 + p) * NK * HD;
    const int kbase = quarter * KQ;

    // staging coords: thread covers rows srow0 (0..31) and srow1 (32..63)
    const int srow0 = t >> 3, sd = (t & 7) * 4;
    const int srow1 = srow0 + 32;

    // ---- step A: Q + K chunk0 ----
    {
        const int qb = (a * 512 + p * 8) * 32 + t;
        float q = g_Qpart[qb] + g_Qpart[qb + 131072]
                + g_Qpart[qb + 262144] + g_Qpart[qb + 393216];
        Q_s[t] = q * 0.17677669529663687f;
    }
    {
        float4 k0 = *(const float4*)&Kt[kb + (kbase + srow0) * 32 + sd];
        float4 k1 = *(const float4*)&Kt[kb + (kbase + srow1) * 32 + sd];
        *(float4*)&K_s[0][srow0 * 36 + sd] = k0;
        *(float4*)&K_s[0][srow1 * 36 + sd] = k1;
    }
    __syncthreads();

    const int kloc = t & 63, qp = t >> 6;
    const int q0 = qp * 2, q1 = q0 + 1;
    const float4* Qs4 = (const float4*)Q_s;

    // ---- step B: prefetch K c1 (rows 64..124), QK c0, STS, sync ----
    float4 p0 = make_float4(0, 0, 0, 0), p1 = make_float4(0, 0, 0, 0);
    if (64 + srow0 < KQ)
        p0 = *(const float4*)&Kt[kb + (kbase + 64 + srow0) * 32 + sd];
    if (64 + srow1 < KQ)
        p1 = *(const float4*)&Kt[kb + (kbase + 64 + srow1) * 32 + sd];
    {
        int kg = kbase + kloc;
        float acc0 = 0, acc1 = 0;
#pragma unroll
        for (int d4i = 0; d4i < 8; d4i++) {
            float4 qa = Qs4[q0 * 8 + d4i];
            float4 qb = Qs4[q1 * 8 + d4i];
            float4 kv = *(const float4*)&K_s[0][kloc * 36 + d4i * 4];
            acc0 += kv.x * qa.x + kv.y * qa.y + kv.z * qa.z + kv.w * qa.w;
            acc1 += kv.x * qb.x + kv.y * qb.y + kv.z * qb.z + kv.w * qb.w;
        }
        S_s[q0 * 128 + kloc] = g_mask[(p * 8 + q0) * NK + kg] ? -1e30f : acc0;
        S_s[q1 * 128 + kloc] = g_mask[(p * 8 + q1) * NK + kg] ? -1e30f : acc1;
    }
    *(float4*)&K_s[1][srow0 * 36 + sd] = p0;
    *(float4*)&K_s[1][srow1 * 36 + sd] = p1;
    __syncthreads();

    // ---- step C: prefetch V c0, QK c1, STS V->buf0, sync ----
    float4 v0 = *(const float4*)&Vt[kb + (kbase + srow0) * 32 + sd];
    float4 v1 = *(const float4*)&Vt[kb + (kbase + srow1) * 32 + sd];
    {
        int kl = 64 + kloc;
        if (kl < KQ) {
            int kg = kbase + kl;
            float acc0 = 0, acc1 = 0;
#pragma unroll
            for (int d4i = 0; d4i < 8; d4i++) {
                float4 qa = Qs4[q0 * 8 + d4i];
                float4 qb = Qs4[q1 * 8 + d4i];
                float4 kv = *(const float4*)&K_s[1][kloc * 36 + d4i * 4];
                acc0 += kv.x * qa.x + kv.y * qa.y + kv.z * qa.z + kv.w * qa.w;
                acc1 += kv.x * qb.x + kv.y * qb.y + kv.z * qb.z + kv.w * qb.w;
            }
            S_s[q0 * 128 + kl] = g_mask[(p * 8 + q0) * NK + kg] ? -1e30f : acc0;
            S_s[q1 * 128 + kl] = g_mask[(p * 8 + q1) * NK + kg] ? -1e30f : acc1;
        }
    }
    *(float4*)&K_s[0][srow0 * 36 + sd] = v0;
    *(float4*)&K_s[0][srow1 * 36 + sd] = v1;
    __syncthreads();

    // ---- step D: per-warp softmax stats (own row; no cross-warp dep) ----
    {
        const int w = t >> 5, l = t & 31;
        float mx = -1e30f;
        for (int k = l; k < KQ; k += 32) mx = fmaxf(mx, S_s[w * 128 + k]);
#pragma unroll
        for (int o = 16; o >= 1; o >>= 1) mx = fmaxf(mx, __shfl_xor_sync(0xffffffffu, mx, o));
        float sm = 0;
        for (int k = l; k < KQ; k += 32) {
            float e = __expf(S_s[w * 128 + k] - mx);
            S_s[w * 128 + k] = e;
            sm += e;
        }
#pragma unroll
        for (int o = 16; o >= 1; o >>= 1) sm += __shfl_xor_sync(0xffffffffu, sm, o);
        if (l == 0)
            g_att_ms[((quarter * 8 + a) * 64 + p) * 8 + w] = make_float2(mx, sm);
        for (int k = KQ + l; k < 128; k += 32) S_s[w * 128 + k] = 0.0f;
    }

    // ---- step E: prefetch V c1, SV c0 from buf0, STS->buf1, sync ----
    float4 v2 = make_float4(0, 0, 0, 0), v3 = make_float4(0, 0, 0, 0);
    if (64 + srow0 < KQ)
        v2 = *(const float4*)&Vt[kb + (kbase + 64 + srow0) * 32 + sd];
    if (64 + srow1 < KQ)
        v3 = *(const float4*)&Vt[kb + (kbase + 64 + srow1) * 32 + sd];

    const int q = t >> 5, d = t & 31;
    float a0 = 0, a1 = 0, a2 = 0, a3 = 0;
    {
        const float* sp = S_s + q * 128;
#pragma unroll
        for (int kk = 0; kk < 64; kk += 4) {
            a0 += sp[kk + 0] * K_s[0][(kk + 0) * 36 + d];
            a1 += sp[kk + 1] * K_s[0][(kk + 1) * 36 + d];
            a2 += sp[kk + 2] * K_s[0][(kk + 2) * 36 + d];
            a3 += sp[kk + 3] * K_s[0][(kk + 3) * 36 + d];
        }
    }
    *(float4*)&K_s[1][srow0 * 36 + sd] = v2;
    *(float4*)&K_s[1][srow1 * 36 + sd] = v3;
    __syncthreads();

    // ---- step F: SV c1 (S_s padded 0 beyond KQ; V rows >= KQ zeroed) ----
    {
        const float* sp = S_s + q * 128 + 64;
#pragma unroll
        for (int kk = 0; kk < 64; kk += 4) {
            a0 += sp[kk + 0] * K_s[1][(kk + 0) * 36 + d];
            a1 += sp[kk + 1] * K_s[1][(kk + 1) * 36 + d];
            a2 += sp[kk + 2] * K_s[1][(kk + 2) * 36 + d];
            a3 += sp[kk + 3] * K_s[1][(kk + 3) * 36 + d];
        }
    }
    g_att_part[(((quarter * 8 + a) * 64 + p) * 8 + q) * 32 + d] = (a0 + a1) + (a2 + a3);
}

// =================================================================
// Kernel 3: qm partial GEMM, k-split 4.  grid (16,8,4) = 512 blocks.
// =================================================================
__global__ __launch_bounds__(256)
void qm_part_kernel(const float* __restrict__ nn_O)
{
    __shared__ float A_s[32 * 65];
    __shared__ float wn_s[32][2][4];
    const int t = threadIdx.x;
    const int b0 = blockIdx.x * 32, j0 = blockIdx.y * 32;
    const int kq = blockIdx.z;
    const int a0 = kq * 2;

    if (t < 64) {
        const int rloc = t >> 1, al = t & 1;
        const int b = b0 + rloc, a = a0 + al;
        float2 ms[4];
        float m = -1e30f;
#pragma unroll
        for (int i = 0; i < 4; i++) {
            ms[i] = g_att_ms[i * 4096 + a * 512 + b];
            m = fmaxf(m, ms[i].x);
        }
        float w[4], den = 0.0f;
#pragma unroll
        for (int i = 0; i < 4; i++) {
            w[i] = __expf(ms[i].x - m);
            den += ms[i].y * w[i];
        }
        float inv = 1.0f / den;
#pragma unroll
        for (int i = 0; i < 4; i++) wn_s[rloc][al][i] = w[i] * inv;
    }
    __syncthreads();

    for (int i = t; i < 2048; i += 256) {
        int r = i >> 6, kk = i & 63;
        int al = kk >> 5, d = kk & 31;
        int b = b0 + r, a = a0 + al;
        float v = 0.0f;
#pragma unroll
        for (int s = 0; s < 4; s++)
            v += g_att_part[((s * 8 + a) * 512 + b) * 32 + d] * wn_s[r][al][s];
        A_s[r * 65 + kk] = v;
    }
    __syncthreads();

    const int rl = t >> 3, jq = t & 7;
    const float* Op = nn_O + (kq * 64) * 256 + j0 + jq * 4;
    float ax = 0, ay = 0, az = 0, aw = 0;
#pragma unroll 8
    for (int k = 0; k < 64; k++) {
        float av = A_s[rl * 65 + k];
        float4 o4 = *(const float4*)&Op[k * 256];
        ax += av * o4.x; ay += av * o4.y;
        az += av * o4.z; aw += av * o4.w;
    }
    *(float4*)&g_qm_part[kq * (BATCH * HDIM) + (b0 + rl) * 256 + j0 + jq * 4] =
        make_float4(ax, ay, az, aw);
}

// =================================================================
// Kernel 4: logits, shuffle-free.  block = (p, 32-k chunk), grid (64,16).
// =================================================================
__global__ __launch_bounds__(256)
void logits_kernel(const float* __restrict__ X, const float* __restrict__ varfeat,
                   const float* __restrict__ nn_A, const float* __restrict__ nn_B,
                   const float* __restrict__ nn_W)
{
    __shared__ float base_s[256][33];
    __shared__ float qm_s[8 * 256];
    __shared__ float w_s[256];
    __shared__ float vf_s[8][32];

    const int t  = threadIdx.x;
    const int p  = blockIdx.x;
    const int k0 = blockIdx.y * 32;

    for (int i = t; i < 2048; i += 256) {
        int base = p * 8 * 256 + i;
        qm_s[i] = g_qm_part[base] + g_qm_part[131072 + base]
                + g_qm_part[262144 + base] + g_qm_part[393216 + base];
    }
    w_s[t] = nn_W[t];
    float a_v[8];
#pragma unroll
    for (int v = 0; v < 8; v++) a_v[v] = nn_A[v * 256 + t];
    const float bB = nn_B[t];
    {
        int v = t >> 5, kk = t & 31;
        vf_s[v][kk] = (k0 + kk < NK) ? varfeat[(p * 8 + v) * NK + k0 + kk] : 0.0f;
    }
    __syncthreads();

    float xv[32];
#pragma unroll
    for (int kk = 0; kk < 32; kk++) {
        int kg = k0 + kk;
        xv[kk] = (kg < NK) ? X[(p * NK + kg) * 256 + t] : 0.0f;
    }
#pragma unroll
    for (int kk = 0; kk < 32; kk++) {
        float vf = bB;
#pragma unroll
        for (int v = 0; v < 8; v++) vf += vf_s[v][kk] * a_v[v];
        base_s[t][kk] = xv[kk] + vf;
    }
    __syncthreads();

    {
        const int w = t >> 5, l = t & 31;
        const int kg = k0 + l;
        const float* qmr = qm_s + w * 256;
        float a0 = 0, a1 = 0, a2 = 0, a3 = 0;
#pragma unroll 16
        for (int h = 0; h < 256; h += 4) {
            a0 += w_s[h + 0] * fast_tanh(base_s[h + 0][l] + qmr[h + 0]);
            a1 += w_s[h + 1] * fast_tanh(base_s[h + 1][l] + qmr[h + 1]);
            a2 += w_s[h + 2] * fast_tanh(base_s[h + 2][l] + qmr[h + 2]);
            a3 += w_s[h + 3] * fast_tanh(base_s[h + 3][l] + qmr[h + 3]);
        }
        if (kg < NK) {
            int idx = (p * 8 + w) * NK + kg;
            g_logit[idx] = g_mask[idx] ? -1e30f : (a0 + a1) + (a2 + a3);
        }
    }
}

// =================================================================
// Kernel 5: choose.  Online softmax, single pass, shuffle reduce.
// =================================================================
__global__ __launch_bounds__(128)
void choose_kernel(float* __restrict__ out_p)
{
    __shared__ float2 warp_ms[4];
    const int r = blockIdx.x, t = threadIdx.x;
    const float* row = g_logit + r * NK;

    float m = -1e30f, s = 0.0f;
    for (int k = t; k < NK; k += 128) {
        float raw = row[k];
        if (raw > -1e29f) {
            float x = tanh_acc(raw) * 10.0f;
            if (x > m) { s = s * __expf(m - x) + 1.0f; m = x; }
            else        s += __expf(x - m);
        }
    }
#pragma unroll
    for (int o = 16; o >= 1; o >>= 1) {
        float om = __shfl_xor_sync(0xffffffffu, m, o);
        float os = __shfl_xor_sync(0xffffffffu, s, o);
        float M = fmaxf(m, om);
        s = s * __expf(m - M) + os * __expf(om - M);
        m = M;
    }
    if ((t & 31) == 0) warp_ms[t >> 5] = make_float2(m, s);
    __syncthreads();
    if (t == 0) {
        float M = fmaxf(fmaxf(warp_ms[0].x, warp_ms[1].x),
                        fmaxf(warp_ms[2].x, warp_ms[3].x));
        float S = warp_ms[0].y * __expf(warp_ms[0].x - M)
                + warp_ms[1].y * __expf(warp_ms[1].x - M)
                + warp_ms[2].y * __expf(warp_ms[2].x - M)
                + warp_ms[3].y * __expf(warp_ms[3].x - M);
        out_p[r] = -logf(S);
    }
}

// =================================================================
extern "C" void kernel_launch(void* const* d_in, const int* in_sizes, int n_in,
                              void* d_out, int out_size)
{
    const float* X       = (const float*)d_in[0];
    const float* Kt      = (const float*)d_in[1];
    const float* Vt      = (const float*)d_in[2];
    const float* query   = (const float*)d_in[3];
    const float* state1  = (const float*)d_in[4];
    const float* state2  = (const float*)d_in[5];
    const float* varfeat = (const float*)d_in[6];
    const void*  mask    = d_in[7];
    const float* nn_Q    = (const float*)d_in[8];
    const float* nn_O    = (const float*)d_in[9];
    const float* nn_A    = (const float*)d_in[10];
    const float* nn_B    = (const float*)d_in[11];
    const float* nn_W    = (const float*)d_in[12];
    const float* W_ih    = (const float*)d_in[13];
    const float* W_hh    = (const float*)d_in[14];
    const float* b_ih    = (const float*)d_in[15];
    const float* b_hh    = (const float*)d_in[16];

    float* out = (float*)d_out;
    float* out_h = out;                       // [512,256]
    float* out_c = out + 512 * 256;           // [512,256]
    float* out_p = out + 2 * 512 * 256;       // [512]

    wt_kernel<<<dim3(32, 16), 256>>>(W_ih, W_hh);
    lstm_part_kernel<<<dim3(16, 8, 4), 256>>>(query, state1, mask);
    lstm_point_kernel<<<128, 256>>>(state2, b_ih, b_hh, out_h, out_c);
    qproj_kernel<<<512, 256>>>(out_h, nn_Q);
    glimpse_part_kernel<<<2048, 256>>>(Kt, Vt);
    qm_part_kernel<<<dim3(16, 8, 4), 256>>>(nn_O);
    logits_kernel<<<dim3(64, 16), 256>>>(X, varfeat, nn_A, nn_B, nn_W);
    choose_kernel<<<512, 128>>>(out_p);
}

// round 14
// speedup vs baseline: 1.0444x; 1.0444x over previous
#include <cuda_runtime.h>
#include <math.h>

#define NPROB  64
#define NRR    8
#define NK     500
#define HDIM   256
#define NHEADS 8
#define HD     32
#define BATCH  512   // NPROB*NRR
#define KQ     125   // NK / 4 k-split for glimpse
#define NSPLIT 4
#define QKS    8     // qproj h-split (32 h per chunk)

// ---------------- scratch (no allocations allowed) ----------------
__device__ float g_WT[512 * 1024];                     // [k][j] transposed LSTM weights
__device__ float g_qm_part[4 * BATCH * HDIM];          // [kq][b][j]
__device__ float g_lstm_part[4 * BATCH * 4 * HDIM];    // [kq][b][1024]
__device__ float g_Qpart[QKS * NHEADS * BATCH * HD];   // [kq8][a][pq][d]
__device__ float g_logit[BATCH * NK];
__device__ unsigned char g_mask[BATCH * NK];
__device__ float g_att_part[NSPLIT * NHEADS * NPROB * NRR * HD];
__device__ float2 g_att_ms[NSPLIT * NHEADS * NPROB * NRR];

__device__ __forceinline__ float fast_tanh(float x) {
    float y;
    asm("tanh.approx.f32 %0, %1;" : "=f"(y) : "f"(x));
    return y;
}
__device__ __forceinline__ float tanh_acc(float x) {
    float e = __expf(2.0f * x);
    return 1.0f - __fdividef(2.0f, e + 1.0f);
}
__device__ __forceinline__ float sigmoidf_(float x) {
    return 1.0f / (1.0f + __expf(-x));
}

// =================================================================
// Kernel 0: transpose LSTM weights into g_WT[k][j].
// =================================================================
__global__ __launch_bounds__(256)
void wt_kernel(const float* __restrict__ W_ih, const float* __restrict__ W_hh)
{
    __shared__ float tile[32][33];
    const int t = threadIdx.x, tx = t & 31, ty = t >> 5;
    const int j0 = blockIdx.x * 32, k0 = blockIdx.y * 32;
    const float* W = (k0 < 256) ? W_ih : W_hh;
    const int kk0 = k0 & 255;
#pragma unroll
    for (int r = ty; r < 32; r += 8)
        tile[r][tx] = W[(j0 + r) * 256 + kk0 + tx];
    __syncthreads();
#pragma unroll
    for (int r = ty; r < 32; r += 8)
        g_WT[(k0 + r) * 1024 + j0 + tx] = tile[tx][r];
}

// =================================================================
// Kernel 1a: LSTM partial GEMM, k-split 4, register-tiled.
// Thread = 4 rows x 4 contiguous j -> 16 FMA per LDG.128.
// Also: distributed mask detect+normalize preamble (500/block).
// =================================================================
__global__ __launch_bounds__(256)
void lstm_part_kernel(const float* __restrict__ query, const float* __restrict__ state1,
                      const void* __restrict__ mraw)
{
    __shared__ float A_s[32 * 132];
    __shared__ int s_i32, s_f32, s_bf16;
    const int t  = threadIdx.x;
    const int b0 = blockIdx.x * 32;
    const int j0 = blockIdx.y * 128;
    const int kq = blockIdx.z;

    if (t == 0) { s_i32 = 1; s_f32 = 1; s_bf16 = 1; }
    __syncthreads();
    {
        const unsigned int* mw = (const unsigned int*)mraw;
        int ok_i32 = 1, ok_f32 = 1, ok_bf16 = 1;
        for (int i = t; i < 2000; i += 256) {
            unsigned int w = mw[i];
            ok_i32  &= (w <= 1u);
            ok_f32  &= (w == 0u || w == 0x3F800000u);
            unsigned int lo = w & 0xFFFFu, hi = w >> 16;
            ok_bf16 &= (lo == 0u || lo == 0x3F80u) && (hi == 0u || hi == 0x3F80u);
        }
        if (!ok_i32)  atomicAnd(&s_i32, 0);
        if (!ok_f32)  atomicAnd(&s_f32, 0);
        if (!ok_bf16) atomicAnd(&s_bf16, 0);
    }

    const float* Asrc = ((kq < 2) ? query : state1) + (kq & 1) * 128;
    for (int i = t; i < 1024; i += 256) {
        int r = i >> 5, c4 = (i & 31) * 4;
        *(float4*)&A_s[r * 132 + c4] = *(const float4*)&Asrc[(b0 + r) * 256 + c4];
    }
    __syncthreads();

    {
        int mode = 0;
        if (s_i32) mode = 1;
        else if (s_f32) mode = 2;
        else if (s_bf16) mode = 3;
        const int bid = (blockIdx.z * 8 + blockIdx.y) * 16 + blockIdx.x;
        const int base = bid * 500;
        for (int i = t; i < 500; i += 256) {
            int idx = base + i;
            unsigned char v;
            if (mode == 1)      v = (((const int*)mraw)[idx] != 0);
            else if (mode == 2) v = (((const unsigned int*)mraw)[idx] != 0u);
            else if (mode == 3) v = (((const unsigned short*)mraw)[idx] != 0u);
            else                v = (((const unsigned char*)mraw)[idx] != 0u);
            g_mask[idx] = v;
        }
    }

    const int w = t >> 5, l = t & 31;
    const int r0 = w * 4;
    const float* Wp = g_WT + (kq * 128) * 1024 + j0 + l * 4;
    float4 acc0 = make_float4(0, 0, 0, 0);
    float4 acc1 = make_float4(0, 0, 0, 0);
    float4 acc2 = make_float4(0, 0, 0, 0);
    float4 acc3 = make_float4(0, 0, 0, 0);
#pragma unroll 4
    for (int k = 0; k < 128; k++) {
        float4 wv = *(const float4*)&Wp[k * 1024];
        float a0 = A_s[(r0 + 0) * 132 + k];
        float a1 = A_s[(r0 + 1) * 132 + k];
        float a2 = A_s[(r0 + 2) * 132 + k];
        float a3 = A_s[(r0 + 3) * 132 + k];
        acc0.x += a0 * wv.x; acc0.y += a0 * wv.y; acc0.z += a0 * wv.z; acc0.w += a0 * wv.w;
        acc1.x += a1 * wv.x; acc1.y += a1 * wv.y; acc1.z += a1 * wv.z; acc1.w += a1 * wv.w;
        acc2.x += a2 * wv.x; acc2.y += a2 * wv.y; acc2.z += a2 * wv.z; acc2.w += a2 * wv.w;
        acc3.x += a3 * wv.x; acc3.y += a3 * wv.y; acc3.z += a3 * wv.z; acc3.w += a3 * wv.w;
    }
    float* outp = g_lstm_part + kq * (BATCH * 1024) + (b0 + r0) * 1024 + j0 + l * 4;
    *(float4*)&outp[0]    = acc0;
    *(float4*)&outp[1024] = acc1;
    *(float4*)&outp[2048] = acc2;
    *(float4*)&outp[3072] = acc3;
}

// =================================================================
// Kernel 1b: LSTM pointwise: combine 4 k-partials + biases, gates.
// =================================================================
__global__ __launch_bounds__(256)
void lstm_point_kernel(const float* __restrict__ state2,
                       const float* __restrict__ b_ih, const float* __restrict__ b_hh,
                       float* __restrict__ out_h, float* __restrict__ out_c)
{
    const int v = blockIdx.x * 256 + threadIdx.x;
    const int b = v >> 6, jv = v & 63;
    const float4* bi = (const float4*)b_ih;
    const float4* bh = (const float4*)b_hh;
    float4 g[4];
#pragma unroll
    for (int gg = 0; gg < 4; gg++) {
        float4 s = bi[gg * 64 + jv], s2 = bh[gg * 64 + jv];
        g[gg] = make_float4(s.x + s2.x, s.y + s2.y, s.z + s2.z, s.w + s2.w);
    }
#pragma unroll
    for (int s = 0; s < 4; s++) {
        const float4* P = (const float4*)(g_lstm_part + s * (BATCH * 1024) + b * 1024);
#pragma unroll
        for (int gg = 0; gg < 4; gg++) {
            float4 pv = P[gg * 64 + jv];
            g[gg].x += pv.x; g[gg].y += pv.y; g[gg].z += pv.z; g[gg].w += pv.w;
        }
    }
    float4 s2 = ((const float4*)state2)[b * 64 + jv];
    float4 c4, h4;
    c4.x = sigmoidf_(g[1].x) * s2.x + sigmoidf_(g[0].x) * tanh_acc(g[2].x);
    c4.y = sigmoidf_(g[1].y) * s2.y + sigmoidf_(g[0].y) * tanh_acc(g[2].y);
    c4.z = sigmoidf_(g[1].z) * s2.z + sigmoidf_(g[0].z) * tanh_acc(g[2].z);
    c4.w = sigmoidf_(g[1].w) * s2.w + sigmoidf_(g[0].w) * tanh_acc(g[2].w);
    h4.x = sigmoidf_(g[3].x) * tanh_acc(c4.x);
    h4.y = sigmoidf_(g[3].y) * tanh_acc(c4.y);
    h4.z = sigmoidf_(g[3].z) * tanh_acc(c4.z);
    h4.w = sigmoidf_(g[3].w) * tanh_acc(c4.w);
    ((float4*)out_h)[b * 64 + jv] = h4;
    ((float4*)out_c)[b * 64 + jv] = c4;
}

// =================================================================
// Kernel 1.5: qproj, h-split 8 + register-tiled lanes.
// grid (16 rt x 8 a x 8 kq) = 1024 blocks x 256 thr.
// warp = 4 rows x 8 d4-groups; 32-deep loop; per h: 1 h-LDG
// (4 sectors) + 1 Q-LDG.128 + 4 FMA/lane.
// =================================================================
__global__ __launch_bounds__(256)
void qproj_kernel(const float* __restrict__ h_in, const float* __restrict__ nn_Q)
{
    const int blk = blockIdx.x;
    const int rt = blk & 15;
    const int a  = (blk >> 4) & 7;
    const int kq = blk >> 7;            // 0..7
    const int t = threadIdx.x;
    const int w = t >> 5, l = t & 31;
    const int rloc = l >> 3, d4 = (l & 7) * 4;
    const int r = rt * 32 + w * 4 + rloc;

    const float* hp = h_in + r * 256 + kq * 32;
    const float* Qp = nn_Q + a * 8192 + (kq * 32) * 32 + d4;
    float4 acc = make_float4(0, 0, 0, 0);
#pragma unroll 8
    for (int h = 0; h < 32; h++) {
        float hv = hp[h];
        float4 qv = *(const float4*)&Qp[h * 32];
        acc.x += hv * qv.x; acc.y += hv * qv.y;
        acc.z += hv * qv.z; acc.w += hv * qv.w;
    }
    *(float4*)&g_Qpart[((kq * 8 + a) * 512 + r) * 32 + d4] = acc;
}

// =================================================================
// Kernel 2: glimpse partials (R11-validated form).
// block = (quarter, head a, problem p), grid 2048.
// =================================================================
__global__ __launch_bounds__(256)
void glimpse_part_kernel(const float* __restrict__ Kt, const float* __restrict__ Vt)
{
    __shared__ __align__(16) float Q_s[8 * 32];
    __shared__ float S_s[8 * 128];
    __shared__ __align__(16) float K_s[64 * 36];

    const int t = threadIdx.x;
    const int quarter = blockIdx.x >> 9;
    const int a = (blockIdx.x >> 6) & 7;
    const int p = blockIdx.x & 63;
    const int kb = (a * 64 + p) * NK * HD;
    const int kbase = quarter * KQ;

    {
        const int qb = (a * 512 + p * 8) * 32 + t;
        float q = 0.0f;
#pragma unroll
        for (int i = 0; i < QKS; i++) q += g_Qpart[qb + i * 131072];
        Q_s[t] = q * 0.17677669529663687f;
    }
    __syncthreads();

    const int kloc = t & 63, qp = t >> 6;
    const int q0 = qp * 2, q1 = q0 + 1;
#pragma unroll
    for (int c0 = 0; c0 < KQ; c0 += 64) {
#pragma unroll
        for (int i = t; i < 512; i += 256) {
            int row = i >> 3, d4 = (i & 7) * 4;
            if (c0 + row < KQ)
                *(float4*)&K_s[row * 36 + d4] =
                    *(const float4*)&Kt[kb + (kbase + c0 + row) * 32 + d4];
        }
        __syncthreads();
        int kl = c0 + kloc;
        if (kl < KQ) {
            int kg = kbase + kl;
            float acc0 = 0, acc1 = 0;
            const float4* Qs4 = (const float4*)Q_s;
#pragma unroll
            for (int d4 = 0; d4 < 8; d4++) {
                float4 qa = Qs4[q0 * 8 + d4];
                float4 qb = Qs4[q1 * 8 + d4];
                float4 kv = *(const float4*)&K_s[kloc * 36 + d4 * 4];
                acc0 += kv.x * qa.x + kv.y * qa.y + kv.z * qa.z + kv.w * qa.w;
                acc1 += kv.x * qb.x + kv.y * qb.y + kv.z * qb.z + kv.w * qb.w;
            }
            S_s[q0 * 128 + kl] = g_mask[(p * 8 + q0) * NK + kg] ? -1e30f : acc0;
            S_s[q1 * 128 + kl] = g_mask[(p * 8 + q1) * NK + kg] ? -1e30f : acc1;
        }
        __syncthreads();
    }

    {
        const int w = t >> 5, l = t & 31;
        float mx = -1e30f;
        for (int k = l; k < KQ; k += 32) mx = fmaxf(mx, S_s[w * 128 + k]);
#pragma unroll
        for (int o = 16; o >= 1; o >>= 1) mx = fmaxf(mx, __shfl_xor_sync(0xffffffffu, mx, o));
        float sm = 0;
        for (int k = l; k < KQ; k += 32) {
            float e = __expf(S_s[w * 128 + k] - mx);
            S_s[w * 128 + k] = e;
            sm += e;
        }
#pragma unroll
        for (int o = 16; o >= 1; o >>= 1) sm += __shfl_xor_sync(0xffffffffu, sm, o);
        if (l == 0)
            g_att_ms[((quarter * 8 + a) * 64 + p) * 8 + w] = make_float2(mx, sm);
        for (int k = KQ + l; k < 128; k += 32) S_s[w * 128 + k] = 0.0f;
    }

    {
        const int q = t >> 5, d = t & 31;
        float a0 = 0, a1 = 0, a2 = 0, a3 = 0;
#pragma unroll
        for (int c0 = 0; c0 < 128; c0 += 64) {
            __syncthreads();
#pragma unroll
            for (int i = t; i < 512; i += 256) {
                int row = i >> 3, d4 = (i & 7) * 4;
                *(float4*)&K_s[row * 36 + d4] = (c0 + row < KQ)
                    ? *(const float4*)&Vt[kb + (kbase + c0 + row) * 32 + d4]
                    : make_float4(0.0f, 0.0f, 0.0f, 0.0f);
            }
            __syncthreads();
            const float* sp = S_s + q * 128 + c0;
#pragma unroll
            for (int kk = 0; kk < 64; kk += 4) {
                a0 += sp[kk + 0] * K_s[(kk + 0) * 36 + d];
                a1 += sp[kk + 1] * K_s[(kk + 1) * 36 + d];
                a2 += sp[kk + 2] * K_s[(kk + 2) * 36 + d];
                a3 += sp[kk + 3] * K_s[(kk + 3) * 36 + d];
            }
        }
        g_att_part[(((quarter * 8 + a) * 64 + p) * 8 + q) * 32 + d] = (a0 + a1) + (a2 + a3);
    }
}

// =================================================================
// Kernel 3: qm partial GEMM, k-split 4.  grid (16,8,4) = 512 blocks.
// =================================================================
__global__ __launch_bounds__(256)
void qm_part_kernel(const float* __restrict__ nn_O)
{
    __shared__ float A_s[32 * 65];
    __shared__ float wn_s[32][2][4];
    const int t = threadIdx.x;
    const int b0 = blockIdx.x * 32, j0 = blockIdx.y * 32;
    const int kq = blockIdx.z;
    const int a0 = kq * 2;

    if (t < 64) {
        const int rloc = t >> 1, al = t & 1;
        const int b = b0 + rloc, a = a0 + al;
        float2 ms[4];
        float m = -1e30f;
#pragma unroll
        for (int i = 0; i < 4; i++) {
            ms[i] = g_att_ms[i * 4096 + a * 512 + b];
            m = fmaxf(m, ms[i].x);
        }
        float w[4], den = 0.0f;
#pragma unroll
        for (int i = 0; i < 4; i++) {
            w[i] = __expf(ms[i].x - m);
            den += ms[i].y * w[i];
        }
        float inv = 1.0f / den;
#pragma unroll
        for (int i = 0; i < 4; i++) wn_s[rloc][al][i] = w[i] * inv;
    }
    __syncthreads();

    for (int i = t; i < 2048; i += 256) {
        int r = i >> 6, kk = i & 63;
        int al = kk >> 5, d = kk & 31;
        int b = b0 + r, a = a0 + al;
        float v = 0.0f;
#pragma unroll
        for (int s = 0; s < 4; s++)
            v += g_att_part[((s * 8 + a) * 512 + b) * 32 + d] * wn_s[r][al][s];
        A_s[r * 65 + kk] = v;
    }
    __syncthreads();

    const int rl = t >> 3, jq = t & 7;
    const float* Op = nn_O + (kq * 64) * 256 + j0 + jq * 4;
    float ax = 0, ay = 0, az = 0, aw = 0;
#pragma unroll 8
    for (int k = 0; k < 64; k++) {
        float av = A_s[rl * 65 + k];
        float4 o4 = *(const float4*)&Op[k * 256];
        ax += av * o4.x; ay += av * o4.y;
        az += av * o4.z; aw += av * o4.w;
    }
    *(float4*)&g_qm_part[kq * (BATCH * HDIM) + (b0 + rl) * 256 + j0 + jq * 4] =
        make_float4(ax, ay, az, aw);
}

// =================================================================
// Kernel 4: logits, shuffle-free.  block = (p, 32-k chunk), grid (64,16).
// =================================================================
__global__ __launch_bounds__(256)
void logits_kernel(const float* __restrict__ X, const float* __restrict__ varfeat,
                   const float* __restrict__ nn_A, const float* __restrict__ nn_B,
                   const float* __restrict__ nn_W)
{
    __shared__ float base_s[256][33];
    __shared__ float qm_s[8 * 256];
    __shared__ float w_s[256];
    __shared__ float vf_s[8][32];

    const int t  = threadIdx.x;
    const int p  = blockIdx.x;
    const int k0 = blockIdx.y * 32;

    for (int i = t; i < 2048; i += 256) {
        int base = p * 8 * 256 + i;
        qm_s[i] = g_qm_part[base] + g_qm_part[131072 + base]
                + g_qm_part[262144 + base] + g_qm_part[393216 + base];
    }
    w_s[t] = nn_W[t];
    float a_v[8];
#pragma unroll
    for (int v = 0; v < 8; v++) a_v[v] = nn_A[v * 256 + t];
    const float bB = nn_B[t];
    {
        int v = t >> 5, kk = t & 31;
        vf_s[v][kk] = (k0 + kk < NK) ? varfeat[(p * 8 + v) * NK + k0 + kk] : 0.0f;
    }
    __syncthreads();

    float xv[32];
#pragma unroll
    for (int kk = 0; kk < 32; kk++) {
        int kg = k0 + kk;
        xv[kk] = (kg < NK) ? X[(p * NK + kg) * 256 + t] : 0.0f;
    }
#pragma unroll
    for (int kk = 0; kk < 32; kk++) {
        float vf = bB;
#pragma unroll
        for (int v = 0; v < 8; v++) vf += vf_s[v][kk] * a_v[v];
        base_s[t][kk] = xv[kk] + vf;
    }
    __syncthreads();

    {
        const int w = t >> 5, l = t & 31;
        const int kg = k0 + l;
        const float* qmr = qm_s + w * 256;
        float a0 = 0, a1 = 0, a2 = 0, a3 = 0;
#pragma unroll 16
        for (int h = 0; h < 256; h += 4) {
            a0 += w_s[h + 0] * fast_tanh(base_s[h + 0][l] + qmr[h + 0]);
            a1 += w_s[h + 1] * fast_tanh(base_s[h + 1][l] + qmr[h + 1]);
            a2 += w_s[h + 2] * fast_tanh(base_s[h + 2][l] + qmr[h + 2]);
            a3 += w_s[h + 3] * fast_tanh(base_s[h + 3][l] + qmr[h + 3]);
        }
        if (kg < NK) {
            int idx = (p * 8 + w) * NK + kg;
            g_logit[idx] = g_mask[idx] ? -1e30f : (a0 + a1) + (a2 + a3);
        }
    }
}

// =================================================================
// Kernel 5: choose.  Online softmax, single pass, shuffle reduce.
// =================================================================
__global__ __launch_bounds__(128)
void choose_kernel(float* __restrict__ out_p)
{
    __shared__ float2 warp_ms[4];
    const int r = blockIdx.x, t = threadIdx.x;
    const float* row = g_logit + r * NK;

    float m = -1e30f, s = 0.0f;
    for (int k = t; k < NK; k += 128) {
        float raw = row[k];
        if (raw > -1e29f) {
            float x = tanh_acc(raw) * 10.0f;
            if (x > m) { s = s * __expf(m - x) + 1.0f; m = x; }
            else        s += __expf(x - m);
        }
    }
#pragma unroll
    for (int o = 16; o >= 1; o >>= 1) {
        float om = __shfl_xor_sync(0xffffffffu, m, o);
        float os = __shfl_xor_sync(0xffffffffu, s, o);
        float M = fmaxf(m, om);
        s = s * __expf(m - M) + os * __expf(om - M);
        m = M;
    }
    if ((t & 31) == 0) warp_ms[t >> 5] = make_float2(m, s);
    __syncthreads();
    if (t == 0) {
        float M = fmaxf(fmaxf(warp_ms[0].x, warp_ms[1].x),
                        fmaxf(warp_ms[2].x, warp_ms[3].x));
        float S = warp_ms[0].y * __expf(warp_ms[0].x - M)
                + warp_ms[1].y * __expf(warp_ms[1].x - M)
                + warp_ms[2].y * __expf(warp_ms[2].x - M)
                + warp_ms[3].y * __expf(warp_ms[3].x - M);
        out_p[r] = -logf(S);
    }
}

// =================================================================
extern "C" void kernel_launch(void* const* d_in, const int* in_sizes, int n_in,
                              void* d_out, int out_size)
{
    const float* X       = (const float*)d_in[0];
    const float* Kt      = (const float*)d_in[1];
    const float* Vt      = (const float*)d_in[2];
    const float* query   = (const float*)d_in[3];
    const float* state1  = (const float*)d_in[4];
    const float* state2  = (const float*)d_in[5];
    const float* varfeat = (const float*)d_in[6];
    const void*  mask    = d_in[7];
    const float* nn_Q    = (const float*)d_in[8];
    const float* nn_O    = (const float*)d_in[9];
    const float* nn_A    = (const float*)d_in[10];
    const float* nn_B    = (const float*)d_in[11];
    const float* nn_W    = (const float*)d_in[12];
    const float* W_ih    = (const float*)d_in[13];
    const float* W_hh    = (const float*)d_in[14];
    const float* b_ih    = (const float*)d_in[15];
    const float* b_hh    = (const float*)d_in[16];

    float* out = (float*)d_out;
    float* out_h = out;                       // [512,256]
    float* out_c = out + 512 * 256;           // [512,256]
    float* out_p = out + 2 * 512 * 256;       // [512]

    wt_kernel<<<dim3(32, 16), 256>>>(W_ih, W_hh);
    lstm_part_kernel<<<dim3(16, 8, 4), 256>>>(query, state1, mask);
    lstm_point_kernel<<<128, 256>>>(state2, b_ih, b_hh, out_h, out_c);
    qproj_kernel<<<1024, 256>>>(out_h, nn_Q);
    glimpse_part_kernel<<<2048, 256>>>(Kt, Vt);
    qm_part_kernel<<<dim3(16, 8, 4), 256>>>(nn_O);
    logits_kernel<<<dim3(64, 16), 256>>>(X, varfeat, nn_A, nn_B, nn_W);
    choose_kernel<<<512, 128>>>(out_p);
}

// round 15
// speedup vs baseline: 1.0672x; 1.0218x over previous
#include <cuda_runtime.h>
#include <math.h>

#define NPROB  64
#define NRR    8
#define NK     500
#define HDIM   256
#define NHEADS 8
#define HD     32
#define BATCH  512   // NPROB*NRR
#define KQ     125   // NK / 4 k-split for glimpse
#define NSPLIT 4
#define QKS    8     // qproj h-split (32 h per chunk)

// ---------------- scratch (no allocations allowed) ----------------
__device__ float g_WT[512 * 1024];                     // [k][j] transposed LSTM weights
__device__ float g_qm_part[4 * BATCH * HDIM];          // [kq][b][j]
__device__ float g_lstm_part[4 * BATCH * 4 * HDIM];    // [kq][b][1024]
__device__ float g_Qpart[QKS * NHEADS * BATCH * HD];   // [hs][a][pq][d]
__device__ float g_logit[BATCH * NK];
__device__ unsigned char g_mask[BATCH * NK];
__device__ float g_att_part[NSPLIT * NHEADS * NPROB * NRR * HD];
__device__ float2 g_att_ms[NSPLIT * NHEADS * NPROB * NRR];

__device__ __forceinline__ float fast_tanh(float x) {
    float y;
    asm("tanh.approx.f32 %0, %1;" : "=f"(y) : "f"(x));
    return y;
}
__device__ __forceinline__ float tanh_acc(float x) {
    float e = __expf(2.0f * x);
    return 1.0f - __fdividef(2.0f, e + 1.0f);
}
__device__ __forceinline__ float sigmoidf_(float x) {
    return 1.0f / (1.0f + __expf(-x));
}

// =================================================================
// Kernel 0: transpose LSTM weights into g_WT[k][j].
// =================================================================
__global__ __launch_bounds__(256)
void wt_kernel(const float* __restrict__ W_ih, const float* __restrict__ W_hh)
{
    __shared__ float tile[32][33];
    const int t = threadIdx.x, tx = t & 31, ty = t >> 5;
    const int j0 = blockIdx.x * 32, k0 = blockIdx.y * 32;
    const float* W = (k0 < 256) ? W_ih : W_hh;
    const int kk0 = k0 & 255;
#pragma unroll
    for (int r = ty; r < 32; r += 8)
        tile[r][tx] = W[(j0 + r) * 256 + kk0 + tx];
    __syncthreads();
#pragma unroll
    for (int r = ty; r < 32; r += 8)
        g_WT[(k0 + r) * 1024 + j0 + tx] = tile[tx][r];
}

// =================================================================
// Kernel 1a: LSTM partial GEMM, k-split 4, register-tiled.
// Thread = 4 rows x 4 contiguous j -> 16 FMA per LDG.128.
// Also: distributed mask detect+normalize preamble (500/block).
// =================================================================
__global__ __launch_bounds__(256)
void lstm_part_kernel(const float* __restrict__ query, const float* __restrict__ state1,
                      const void* __restrict__ mraw)
{
    __shared__ float A_s[32 * 132];
    __shared__ int s_i32, s_f32, s_bf16;
    const int t  = threadIdx.x;
    const int b0 = blockIdx.x * 32;
    const int j0 = blockIdx.y * 128;
    const int kq = blockIdx.z;

    if (t == 0) { s_i32 = 1; s_f32 = 1; s_bf16 = 1; }
    __syncthreads();
    {
        const unsigned int* mw = (const unsigned int*)mraw;
        int ok_i32 = 1, ok_f32 = 1, ok_bf16 = 1;
        for (int i = t; i < 2000; i += 256) {
            unsigned int w = mw[i];
            ok_i32  &= (w <= 1u);
            ok_f32  &= (w == 0u || w == 0x3F800000u);
            unsigned int lo = w & 0xFFFFu, hi = w >> 16;
            ok_bf16 &= (lo == 0u || lo == 0x3F80u) && (hi == 0u || hi == 0x3F80u);
        }
        if (!ok_i32)  atomicAnd(&s_i32, 0);
        if (!ok_f32)  atomicAnd(&s_f32, 0);
        if (!ok_bf16) atomicAnd(&s_bf16, 0);
    }

    const float* Asrc = ((kq < 2) ? query : state1) + (kq & 1) * 128;
    for (int i = t; i < 1024; i += 256) {
        int r = i >> 5, c4 = (i & 31) * 4;
        *(float4*)&A_s[r * 132 + c4] = *(const float4*)&Asrc[(b0 + r) * 256 + c4];
    }
    __syncthreads();

    {
        int mode = 0;
        if (s_i32) mode = 1;
        else if (s_f32) mode = 2;
        else if (s_bf16) mode = 3;
        const int bid = (blockIdx.z * 8 + blockIdx.y) * 16 + blockIdx.x;
        const int base = bid * 500;
        for (int i = t; i < 500; i += 256) {
            int idx = base + i;
            unsigned char v;
            if (mode == 1)      v = (((const int*)mraw)[idx] != 0);
            else if (mode == 2) v = (((const unsigned int*)mraw)[idx] != 0u);
            else if (mode == 3) v = (((const unsigned short*)mraw)[idx] != 0u);
            else                v = (((const unsigned char*)mraw)[idx] != 0u);
            g_mask[idx] = v;
        }
    }

    const int w = t >> 5, l = t & 31;
    const int r0 = w * 4;
    const float* Wp = g_WT + (kq * 128) * 1024 + j0 + l * 4;
    float4 acc0 = make_float4(0, 0, 0, 0);
    float4 acc1 = make_float4(0, 0, 0, 0);
    float4 acc2 = make_float4(0, 0, 0, 0);
    float4 acc3 = make_float4(0, 0, 0, 0);
#pragma unroll 4
    for (int k = 0; k < 128; k++) {
        float4 wv = *(const float4*)&Wp[k * 1024];
        float a0 = A_s[(r0 + 0) * 132 + k];
        float a1 = A_s[(r0 + 1) * 132 + k];
        float a2 = A_s[(r0 + 2) * 132 + k];
        float a3 = A_s[(r0 + 3) * 132 + k];
        acc0.x += a0 * wv.x; acc0.y += a0 * wv.y; acc0.z += a0 * wv.z; acc0.w += a0 * wv.w;
        acc1.x += a1 * wv.x; acc1.y += a1 * wv.y; acc1.z += a1 * wv.z; acc1.w += a1 * wv.w;
        acc2.x += a2 * wv.x; acc2.y += a2 * wv.y; acc2.z += a2 * wv.z; acc2.w += a2 * wv.w;
        acc3.x += a3 * wv.x; acc3.y += a3 * wv.y; acc3.z += a3 * wv.z; acc3.w += a3 * wv.w;
    }
    float* outp = g_lstm_part + kq * (BATCH * 1024) + (b0 + r0) * 1024 + j0 + l * 4;
    *(float4*)&outp[0]    = acc0;
    *(float4*)&outp[1024] = acc1;
    *(float4*)&outp[2048] = acc2;
    *(float4*)&outp[3072] = acc3;
}

// =================================================================
// Kernel 1b: LSTM pointwise: combine 4 k-partials + biases, gates.
// =================================================================
__global__ __launch_bounds__(256)
void lstm_point_kernel(const float* __restrict__ state2,
                       const float* __restrict__ b_ih, const float* __restrict__ b_hh,
                       float* __restrict__ out_h, float* __restrict__ out_c)
{
    const int v = blockIdx.x * 256 + threadIdx.x;
    const int b = v >> 6, jv = v & 63;
    const float4* bi = (const float4*)b_ih;
    const float4* bh = (const float4*)b_hh;
    float4 g[4];
#pragma unroll
    for (int gg = 0; gg < 4; gg++) {
        float4 s = bi[gg * 64 + jv], s2 = bh[gg * 64 + jv];
        g[gg] = make_float4(s.x + s2.x, s.y + s2.y, s.z + s2.z, s.w + s2.w);
    }
#pragma unroll
    for (int s = 0; s < 4; s++) {
        const float4* P = (const float4*)(g_lstm_part + s * (BATCH * 1024) + b * 1024);
#pragma unroll
        for (int gg = 0; gg < 4; gg++) {
            float4 pv = P[gg * 64 + jv];
            g[gg].x += pv.x; g[gg].y += pv.y; g[gg].z += pv.z; g[gg].w += pv.w;
        }
    }
    float4 s2 = ((const float4*)state2)[b * 64 + jv];
    float4 c4, h4;
    c4.x = sigmoidf_(g[1].x) * s2.x + sigmoidf_(g[0].x) * tanh_acc(g[2].x);
    c4.y = sigmoidf_(g[1].y) * s2.y + sigmoidf_(g[0].y) * tanh_acc(g[2].y);
    c4.z = sigmoidf_(g[1].z) * s2.z + sigmoidf_(g[0].z) * tanh_acc(g[2].z);
    c4.w = sigmoidf_(g[1].w) * s2.w + sigmoidf_(g[0].w) * tanh_acc(g[2].w);
    h4.x = sigmoidf_(g[3].x) * tanh_acc(c4.x);
    h4.y = sigmoidf_(g[3].y) * tanh_acc(c4.y);
    h4.z = sigmoidf_(g[3].z) * tanh_acc(c4.z);
    h4.w = sigmoidf_(g[3].w) * tanh_acc(c4.w);
    ((float4*)out_h)[b * 64 + jv] = h4;
    ((float4*)out_c)[b * 64 + jv] = c4;
}

// =================================================================
// Kernel 1.5: qproj, transposed-h broadcast layout.
// grid (16 rt, 8 hs, 2 ag) = 256 blocks x 256 thr.
// Block = (32 rows, 32 h, 4 heads).  h staged transposed h_s[h][r].
// Warp = (head a, 16-row half); lane = d.  Per h-step:
// 1 coalesced Q-LDG + 4 broadcast LDS.128 + 16 FMA per lane.
// =================================================================
__global__ __launch_bounds__(256)
void qproj_kernel(const float* __restrict__ h_in, const float* __restrict__ nn_Q)
{
    __shared__ __align__(16) float h_s[32][36];   // [h][r]
    const int t  = threadIdx.x;
    const int rt = blockIdx.x;        // 0..15 (32 rows each)
    const int hs = blockIdx.y;        // 0..7  (32 h each)
    const int ag = blockIdx.z;        // 0..1  (4 heads each)

    // stage h transposed: read coalesced over h, write h_s[h][r]
    for (int i = t; i < 1024; i += 256) {
        int r = i >> 5, h = i & 31;
        h_s[h][r] = h_in[(rt * 32 + r) * 256 + hs * 32 + h];
    }
    __syncthreads();

    const int w = t >> 5, d = t & 31;
    const int a = ag * 4 + (w >> 1);
    const int rhalf = (w & 1) * 16;
    const float* Qp = nn_Q + a * 8192 + (hs * 32) * 32 + d;

    float acc[16];
#pragma unroll
    for (int r = 0; r < 16; r++) acc[r] = 0.0f;
#pragma unroll 4
    for (int h = 0; h < 32; h++) {
        float qv = Qp[h * 32];
        const float4* hr = (const float4*)&h_s[h][rhalf];
        float4 v0 = hr[0], v1 = hr[1], v2 = hr[2], v3 = hr[3];
        acc[0]  += v0.x * qv; acc[1]  += v0.y * qv; acc[2]  += v0.z * qv; acc[3]  += v0.w * qv;
        acc[4]  += v1.x * qv; acc[5]  += v1.y * qv; acc[6]  += v1.z * qv; acc[7]  += v1.w * qv;
        acc[8]  += v2.x * qv; acc[9]  += v2.y * qv; acc[10] += v2.z * qv; acc[11] += v2.w * qv;
        acc[12] += v3.x * qv; acc[13] += v3.y * qv; acc[14] += v3.z * qv; acc[15] += v3.w * qv;
    }
    float* outp = g_Qpart + ((hs * 8 + a) * 512 + rt * 32 + rhalf) * 32 + d;
#pragma unroll
    for (int r = 0; r < 16; r++) outp[r * 32] = acc[r];
}

// =================================================================
// Kernel 2: glimpse partials (R11-validated form).
// block = (quarter, head a, problem p), grid 2048.
// =================================================================
__global__ __launch_bounds__(256)
void glimpse_part_kernel(const float* __restrict__ Kt, const float* __restrict__ Vt)
{
    __shared__ __align__(16) float Q_s[8 * 32];
    __shared__ float S_s[8 * 128];
    __shared__ __align__(16) float K_s[64 * 36];

    const int t = threadIdx.x;
    const int quarter = blockIdx.x >> 9;
    const int a = (blockIdx.x >> 6) & 7;
    const int p = blockIdx.x & 63;
    const int kb = (a * 64 + p) * NK * HD;
    const int kbase = quarter * KQ;

    {
        const int qb = (a * 512 + p * 8) * 32 + t;
        float q = 0.0f;
#pragma unroll
        for (int i = 0; i < QKS; i++) q += g_Qpart[qb + i * 131072];
        Q_s[t] = q * 0.17677669529663687f;
    }
    __syncthreads();

    const int kloc = t & 63, qp = t >> 6;
    const int q0 = qp * 2, q1 = q0 + 1;
#pragma unroll
    for (int c0 = 0; c0 < KQ; c0 += 64) {
#pragma unroll
        for (int i = t; i < 512; i += 256) {
            int row = i >> 3, d4 = (i & 7) * 4;
            if (c0 + row < KQ)
                *(float4*)&K_s[row * 36 + d4] =
                    *(const float4*)&Kt[kb + (kbase + c0 + row) * 32 + d4];
        }
        __syncthreads();
        int kl = c0 + kloc;
        if (kl < KQ) {
            int kg = kbase + kl;
            float acc0 = 0, acc1 = 0;
            const float4* Qs4 = (const float4*)Q_s;
#pragma unroll
            for (int d4 = 0; d4 < 8; d4++) {
                float4 qa = Qs4[q0 * 8 + d4];
                float4 qb = Qs4[q1 * 8 + d4];
                float4 kv = *(const float4*)&K_s[kloc * 36 + d4 * 4];
                acc0 += kv.x * qa.x + kv.y * qa.y + kv.z * qa.z + kv.w * qa.w;
                acc1 += kv.x * qb.x + kv.y * qb.y + kv.z * qb.z + kv.w * qb.w;
            }
            S_s[q0 * 128 + kl] = g_mask[(p * 8 + q0) * NK + kg] ? -1e30f : acc0;
            S_s[q1 * 128 + kl] = g_mask[(p * 8 + q1) * NK + kg] ? -1e30f : acc1;
        }
        __syncthreads();
    }

    {
        const int w = t >> 5, l = t & 31;
        float mx = -1e30f;
        for (int k = l; k < KQ; k += 32) mx = fmaxf(mx, S_s[w * 128 + k]);
#pragma unroll
        for (int o = 16; o >= 1; o >>= 1) mx = fmaxf(mx, __shfl_xor_sync(0xffffffffu, mx, o));
        float sm = 0;
        for (int k = l; k < KQ; k += 32) {
            float e = __expf(S_s[w * 128 + k] - mx);
            S_s[w * 128 + k] = e;
            sm += e;
        }
#pragma unroll
        for (int o = 16; o >= 1; o >>= 1) sm += __shfl_xor_sync(0xffffffffu, sm, o);
        if (l == 0)
            g_att_ms[((quarter * 8 + a) * 64 + p) * 8 + w] = make_float2(mx, sm);
        for (int k = KQ + l; k < 128; k += 32) S_s[w * 128 + k] = 0.0f;
    }

    {
        const int q = t >> 5, d = t & 31;
        float a0 = 0, a1 = 0, a2 = 0, a3 = 0;
#pragma unroll
        for (int c0 = 0; c0 < 128; c0 += 64) {
            __syncthreads();
#pragma unroll
            for (int i = t; i < 512; i += 256) {
                int row = i >> 3, d4 = (i & 7) * 4;
                *(float4*)&K_s[row * 36 + d4] = (c0 + row < KQ)
                    ? *(const float4*)&Vt[kb + (kbase + c0 + row) * 32 + d4]
                    : make_float4(0.0f, 0.0f, 0.0f, 0.0f);
            }
            __syncthreads();
            const float* sp = S_s + q * 128 + c0;
#pragma unroll
            for (int kk = 0; kk < 64; kk += 4) {
                a0 += sp[kk + 0] * K_s[(kk + 0) * 36 + d];
                a1 += sp[kk + 1] * K_s[(kk + 1) * 36 + d];
                a2 += sp[kk + 2] * K_s[(kk + 2) * 36 + d];
                a3 += sp[kk + 3] * K_s[(kk + 3) * 36 + d];
            }
        }
        g_att_part[(((quarter * 8 + a) * 64 + p) * 8 + q) * 32 + d] = (a0 + a1) + (a2 + a3);
    }
}

// =================================================================
// Kernel 3: qm partial GEMM, k-split 4.  grid (16,8,4) = 512 blocks.
// =================================================================
__global__ __launch_bounds__(256)
void qm_part_kernel(const float* __restrict__ nn_O)
{
    __shared__ float A_s[32 * 65];
    __shared__ float wn_s[32][2][4];
    const int t = threadIdx.x;
    const int b0 = blockIdx.x * 32, j0 = blockIdx.y * 32;
    const int kq = blockIdx.z;
    const int a0 = kq * 2;

    if (t < 64) {
        const int rloc = t >> 1, al = t & 1;
        const int b = b0 + rloc, a = a0 + al;
        float2 ms[4];
        float m = -1e30f;
#pragma unroll
        for (int i = 0; i < 4; i++) {
            ms[i] = g_att_ms[i * 4096 + a * 512 + b];
            m = fmaxf(m, ms[i].x);
        }
        float w[4], den = 0.0f;
#pragma unroll
        for (int i = 0; i < 4; i++) {
            w[i] = __expf(ms[i].x - m);
            den += ms[i].y * w[i];
        }
        float inv = 1.0f / den;
#pragma unroll
        for (int i = 0; i < 4; i++) wn_s[rloc][al][i] = w[i] * inv;
    }
    __syncthreads();

    for (int i = t; i < 2048; i += 256) {
        int r = i >> 6, kk = i & 63;
        int al = kk >> 5, d = kk & 31;
        int b = b0 + r, a = a0 + al;
        float v = 0.0f;
#pragma unroll
        for (int s = 0; s < 4; s++)
            v += g_att_part[((s * 8 + a) * 512 + b) * 32 + d] * wn_s[r][al][s];
        A_s[r * 65 + kk] = v;
    }
    __syncthreads();

    const int rl = t >> 3, jq = t & 7;
    const float* Op = nn_O + (kq * 64) * 256 + j0 + jq * 4;
    float ax = 0, ay = 0, az = 0, aw = 0;
#pragma unroll 8
    for (int k = 0; k < 64; k++) {
        float av = A_s[rl * 65 + k];
        float4 o4 = *(const float4*)&Op[k * 256];
        ax += av * o4.x; ay += av * o4.y;
        az += av * o4.z; aw += av * o4.w;
    }
    *(float4*)&g_qm_part[kq * (BATCH * HDIM) + (b0 + rl) * 256 + j0 + jq * 4] =
        make_float4(ax, ay, az, aw);
}

// =================================================================
// Kernel 4: logits, shuffle-free.  block = (p, 32-k chunk), grid (64,16).
// =================================================================
__global__ __launch_bounds__(256)
void logits_kernel(const float* __restrict__ X, const float* __restrict__ varfeat,
                   const float* __restrict__ nn_A, const float* __restrict__ nn_B,
                   const float* __restrict__ nn_W)
{
    __shared__ float base_s[256][33];
    __shared__ float qm_s[8 * 256];
    __shared__ float w_s[256];
    __shared__ float vf_s[8][32];

    const int t  = threadIdx.x;
    const int p  = blockIdx.x;
    const int k0 = blockIdx.y * 32;

    for (int i = t; i < 2048; i += 256) {
        int base = p * 8 * 256 + i;
        qm_s[i] = g_qm_part[base] + g_qm_part[131072 + base]
                + g_qm_part[262144 + base] + g_qm_part[393216 + base];
    }
    w_s[t] = nn_W[t];
    float a_v[8];
#pragma unroll
    for (int v = 0; v < 8; v++) a_v[v] = nn_A[v * 256 + t];
    const float bB = nn_B[t];
    {
        int v = t >> 5, kk = t & 31;
        vf_s[v][kk] = (k0 + kk < NK) ? varfeat[(p * 8 + v) * NK + k0 + kk] : 0.0f;
    }
    __syncthreads();

    float xv[32];
#pragma unroll
    for (int kk = 0; kk < 32; kk++) {
        int kg = k0 + kk;
        xv[kk] = (kg < NK) ? X[(p * NK + kg) * 256 + t] : 0.0f;
    }
#pragma unroll
    for (int kk = 0; kk < 32; kk++) {
        float vf = bB;
#pragma unroll
        for (int v = 0; v < 8; v++) vf += vf_s[v][kk] * a_v[v];
        base_s[t][kk] = xv[kk] + vf;
    }
    __syncthreads();

    {
        const int w = t >> 5, l = t & 31;
        const int kg = k0 + l;
        const float* qmr = qm_s + w * 256;
        float a0 = 0, a1 = 0, a2 = 0, a3 = 0;
#pragma unroll 16
        for (int h = 0; h < 256; h += 4) {
            a0 += w_s[h + 0] * fast_tanh(base_s[h + 0][l] + qmr[h + 0]);
            a1 += w_s[h + 1] * fast_tanh(base_s[h + 1][l] + qmr[h + 1]);
            a2 += w_s[h + 2] * fast_tanh(base_s[h + 2][l] + qmr[h + 2]);
            a3 += w_s[h + 3] * fast_tanh(base_s[h + 3][l] + qmr[h + 3]);
        }
        if (kg < NK) {
            int idx = (p * 8 + w) * NK + kg;
            g_logit[idx] = g_mask[idx] ? -1e30f : (a0 + a1) + (a2 + a3);
        }
    }
}

// =================================================================
// Kernel 5: choose.  Online softmax, single pass, shuffle reduce.
// =================================================================
__global__ __launch_bounds__(128)
void choose_kernel(float* __restrict__ out_p)
{
    __shared__ float2 warp_ms[4];
    const int r = blockIdx.x, t = threadIdx.x;
    const float* row = g_logit + r * NK;

    float m = -1e30f, s = 0.0f;
    for (int k = t; k < NK; k += 128) {
        float raw = row[k];
        if (raw > -1e29f) {
            float x = tanh_acc(raw) * 10.0f;
            if (x > m) { s = s * __expf(m - x) + 1.0f; m = x; }
            else        s += __expf(x - m);
        }
    }
#pragma unroll
    for (int o = 16; o >= 1; o >>= 1) {
        float om = __shfl_xor_sync(0xffffffffu, m, o);
        float os = __shfl_xor_sync(0xffffffffu, s, o);
        float M = fmaxf(m, om);
        s = s * __expf(m - M) + os * __expf(om - M);
        m = M;
    }
    if ((t & 31) == 0) warp_ms[t >> 5] = make_float2(m, s);
    __syncthreads();
    if (t == 0) {
        float M = fmaxf(fmaxf(warp_ms[0].x, warp_ms[1].x),
                        fmaxf(warp_ms[2].x, warp_ms[3].x));
        float S = warp_ms[0].y * __expf(warp_ms[0].x - M)
                + warp_ms[1].y * __expf(warp_ms[1].x - M)
                + warp_ms[2].y * __expf(warp_ms[2].x - M)
                + warp_ms[3].y * __expf(warp_ms[3].x - M);
        out_p[r] = -logf(S);
    }
}

// =================================================================
extern "C" void kernel_launch(void* const* d_in, const int* in_sizes, int n_in,
                              void* d_out, int out_size)
{
    const float* X       = (const float*)d_in[0];
    const float* Kt      = (const float*)d_in[1];
    const float* Vt      = (const float*)d_in[2];
    const float* query   = (const float*)d_in[3];
    const float* state1  = (const float*)d_in[4];
    const float* state2  = (const float*)d_in[5];
    const float* varfeat = (const float*)d_in[6];
    const void*  mask    = d_in[7];
    const float* nn_Q    = (const float*)d_in[8];
    const float* nn_O    = (const float*)d_in[9];
    const float* nn_A    = (const float*)d_in[10];
    const float* nn_B    = (const float*)d_in[11];
    const float* nn_W    = (const float*)d_in[12];
    const float* W_ih    = (const float*)d_in[13];
    const float* W_hh    = (const float*)d_in[14];
    const float* b_ih    = (const float*)d_in[15];
    const float* b_hh    = (const float*)d_in[16];

    float* out = (float*)d_out;
    float* out_h = out;                       // [512,256]
    float* out_c = out + 512 * 256;           // [512,256]
    float* out_p = out + 2 * 512 * 256;       // [512]

    wt_kernel<<<dim3(32, 16), 256>>>(W_ih, W_hh);
    lstm_part_kernel<<<dim3(16, 8, 4), 256>>>(query, state1, mask);
    lstm_point_kernel<<<128, 256>>>(state2, b_ih, b_hh, out_h, out_c);
    qproj_kernel<<<dim3(16, 8, 2), 256>>>(out_h, nn_Q);
    glimpse_part_kernel<<<2048, 256>>>(Kt, Vt);
    qm_part_kernel<<<dim3(16, 8, 4), 256>>>(nn_O);
    logits_kernel<<<dim3(64, 16), 256>>>(X, varfeat, nn_A, nn_B, nn_W);
    choose_kernel<<<512, 128>>>(out_p);
}